// round 9
// baseline (speedup 1.0000x reference)
#include <cuda_runtime.h>

// RNNBlock: h_t = tanh(x_t @ Wx[t] + h_{t-1} @ Wh[t]), h_{-1}=0
// B=512, S=512, D=256, fp32.
//
// K0a: pack Wx -> tf32 (8-warp layout, for K1).
// K0b: pack Wh -> tf32 (32-global-warp layout, for clustered K2).
// K1:  out = x @ Wx (parallel, 16x512 CTAs).
// K2:  recurrence. 32 clusters x 2 CTAs. Cluster = 16 batch rows; CTA rank r
//      computes cols [128r,128r+128) (16 warps x 8 cols). h for next step is
//      written into BOTH CTAs' double-buffered A-frag smem (DSMEM st for the
//      peer); one barrier.cluster per step publishes it. Weights via depth-8
//      register ring (1 LDG.64/kit/warp); A-frags 1 LDS.128/kit/warp.

#define S_LEN 512
#define B_SZ  512
#define DIM   256
#define TM1   32
#define TM2   16
#define SSTRIDE 260            // K1 xs stride
#define ZSTRIDE 132            // K2 zs stride (128 cols + pad)
#define WT_STRIDE 65536        // u32 per timestep of packed weights
#define PFD 8                  // weight ring depth (kits)

__device__ unsigned g_WxP[(size_t)S_LEN * WT_STRIDE];
__device__ unsigned g_WhP[(size_t)S_LEN * WT_STRIDE];

__device__ __forceinline__ unsigned f2tf32(float f) {
    unsigned u;
    asm("cvt.rna.tf32.f32 %0, %1;" : "=r"(u) : "f"(f));
    return u;
}

__device__ __forceinline__ void mma_tf32(float c[4],
                                         unsigned a0, unsigned a1, unsigned a2, unsigned a3,
                                         unsigned b0, unsigned b1) {
    asm volatile(
        "mma.sync.aligned.m16n8k8.row.col.f32.tf32.tf32.f32 "
        "{%0,%1,%2,%3}, {%4,%5,%6,%7}, {%8,%9}, {%0,%1,%2,%3};"
        : "+f"(c[0]), "+f"(c[1]), "+f"(c[2]), "+f"(c[3])
        : "r"(a0), "r"(a1), "r"(a2), "r"(a3), "r"(b0), "r"(b1));
}

__device__ __forceinline__ float fast_tanh(float x) {
    x = fminf(fmaxf(x, -15.f), 15.f);
    float e = __expf(2.f * x);
    return __fdividef(e - 1.f, e + 1.f);
}

__device__ __forceinline__ void cp_async16(void* dst_smem, const void* src) {
    unsigned d = (unsigned)__cvta_generic_to_shared(dst_smem);
    asm volatile("cp.async.cg.shared.global [%0], [%1], 16;" :: "r"(d), "l"(src));
}
#define CP_COMMIT() asm volatile("cp.async.commit_group;")
#define CP_WAIT1()  asm volatile("cp.async.wait_group 1;" ::: "memory")
#define CLUSTER_BAR() do { \
    asm volatile("barrier.cluster.arrive.aligned;" ::: "memory"); \
    asm volatile("barrier.cluster.wait.aligned;"   ::: "memory"); \
} while (0)

__device__ __forceinline__ unsigned ctarank() {
    unsigned r; asm("mov.u32 %0, %%cluster_ctarank;" : "=r"(r)); return r;
}
__device__ __forceinline__ void st_remote_u32(unsigned local_saddr, unsigned peer, unsigned v) {
    unsigned raddr;
    asm volatile("mapa.shared::cluster.u32 %0, %1, %2;" : "=r"(raddr) : "r"(local_saddr), "r"(peer));
    asm volatile("st.shared::cluster.u32 [%0], %1;" :: "r"(raddr), "r"(v) : "memory");
}

// ---------- K0a: pack Wx for K1 (8-warp layout) -----------------------------------
// u32 slot: t*65536 + w*8192 + kit*256 + lane*8 + pair*4
__global__ void __launch_bounds__(256)
pack_wx(const float* __restrict__ W, unsigned* __restrict__ P) {
    unsigned idx  = blockIdx.x * 256u + threadIdx.x;
    unsigned pair = idx & 1, lane = (idx >> 1) & 31, kit = (idx >> 6) & 31,
             w    = (idx >> 11) & 7, t = idx >> 14;
    unsigned g = lane >> 2, tig = lane & 3, k0 = kit * 8;
    const float* Wt = W + (size_t)t * DIM * DIM;
    unsigned n0 = w * 32 + pair * 16 + g;
    uint4 v;
    v.x = f2tf32(Wt[(k0 + tig)     * DIM + n0]);
    v.y = f2tf32(Wt[(k0 + tig + 4) * DIM + n0]);
    v.z = f2tf32(Wt[(k0 + tig)     * DIM + n0 + 8]);
    v.w = f2tf32(Wt[(k0 + tig + 4) * DIM + n0 + 8]);
    reinterpret_cast<uint4*>(P)[idx] = v;
}

// ---------- K0b: pack Wh for clustered K2 (32 global warps x 8 cols) --------------
// uint2 slot: idx = t*32768 + gw*1024 + kit*32 + lane   (u32 off = idx*2)
// contents: { W[k0+tig][n], W[k0+tig+4][n] },  n = gw*8 + g
__global__ void __launch_bounds__(256)
pack_wh(const float* __restrict__ W, unsigned* __restrict__ P) {
    unsigned idx  = blockIdx.x * 256u + threadIdx.x;   // uint2 slots, 16,777,216
    unsigned lane = idx & 31, kit = (idx >> 5) & 31,
             gw   = (idx >> 10) & 31, t = idx >> 15;
    unsigned g = lane >> 2, tig = lane & 3, k0 = kit * 8;
    const float* Wt = W + (size_t)t * DIM * DIM;
    unsigned n = gw * 8 + g;
    uint2 v;
    v.x = f2tf32(Wt[(k0 + tig)     * DIM + n]);
    v.y = f2tf32(Wt[(k0 + tig + 4) * DIM + n]);
    reinterpret_cast<uint2*>(P)[idx] = v;
}

// ---------- K1: Z = x @ Wx (unchanged) --------------------------------------------
__global__ void __launch_bounds__(256)
rnn_k1(const float* __restrict__ x, float* __restrict__ out) {
    __shared__ unsigned xs[TM1 * SSTRIDE];
    const int bt = blockIdx.x, t = blockIdx.y, tid = threadIdx.x;
    const int w = tid >> 5, lane = tid & 31, g = lane >> 2, tig = lane & 3;
    const int b0r = bt * TM1;

    for (int i = tid; i < TM1 * (DIM / 4); i += 256) {
        int r = i >> 6, c4 = i & 63;
        float4 v = *reinterpret_cast<const float4*>(
            x + ((size_t)(b0r + r) * S_LEN + t) * DIM + c4 * 4);
        uint4 u = make_uint4(f2tf32(v.x), f2tf32(v.y), f2tf32(v.z), f2tf32(v.w));
        *reinterpret_cast<uint4*>(&xs[r * SSTRIDE + c4 * 4]) = u;
    }
    __syncthreads();

    float acc[2][4][4] = {};
    const unsigned* Bp = g_WxP + (size_t)t * WT_STRIDE + w * 8192 + lane * 8;
#pragma unroll
    for (int kit = 0; kit < 32; kit++) {
        uint4 p0 = *reinterpret_cast<const uint4*>(Bp + kit * 256);
        uint4 p1 = *reinterpret_cast<const uint4*>(Bp + kit * 256 + 4);
        const int k0 = kit * 8;
        unsigned a[2][4];
#pragma unroll
        for (int mi = 0; mi < 2; mi++) {
            int r0 = mi * 16 + g;
            a[mi][0] = xs[r0 * SSTRIDE + k0 + tig];
            a[mi][1] = xs[(r0 + 8) * SSTRIDE + k0 + tig];
            a[mi][2] = xs[r0 * SSTRIDE + k0 + tig + 4];
            a[mi][3] = xs[(r0 + 8) * SSTRIDE + k0 + tig + 4];
        }
#pragma unroll
        for (int mi = 0; mi < 2; mi++) {
            mma_tf32(acc[mi][0], a[mi][0], a[mi][1], a[mi][2], a[mi][3], p0.x, p0.y);
            mma_tf32(acc[mi][1], a[mi][0], a[mi][1], a[mi][2], a[mi][3], p0.z, p0.w);
            mma_tf32(acc[mi][2], a[mi][0], a[mi][1], a[mi][2], a[mi][3], p1.x, p1.y);
            mma_tf32(acc[mi][3], a[mi][0], a[mi][1], a[mi][2], a[mi][3], p1.z, p1.w);
        }
    }

#pragma unroll
    for (int mi = 0; mi < 2; mi++)
#pragma unroll
        for (int half = 0; half < 2; half++) {
            int r = b0r + mi * 16 + g + half * 8;
            size_t base = ((size_t)r * S_LEN + t) * DIM;
#pragma unroll
            for (int nt = 0; nt < 4; nt++) {
                int c = w * 32 + nt * 8 + tig * 2;
                *reinterpret_cast<float2*>(out + base + c) =
                    make_float2(acc[mi][nt][half * 2], acc[mi][nt][half * 2 + 1]);
            }
        }
}

// ---------- K2: clustered recurrence ----------------------------------------------
// smem: apack[2][4096] u32 (A-frags in mma register order, double-buffered),
//       zs[2][16*ZSTRIDE] float (this CTA's 128 Z cols, double-buffered).
// apack element: kit*128 + lane*4 + j  (j0=A[g][k0+tig], j1=A[g+8][k0+tig],
//                j2=A[g][k0+tig+4], j3=A[g+8][k0+tig+4];  lane=(g<<2)|tig)
__global__ void __launch_bounds__(512, 1) __cluster_dims__(2, 1, 1)
rnn_k2(float* __restrict__ out) {
    extern __shared__ unsigned smemraw[];
    unsigned* apack = smemraw;                                // 2*4096 u32
    float*    zs    = reinterpret_cast<float*>(smemraw + 8192);
    const int ZSZ = TM2 * ZSTRIDE;

    const int tid  = threadIdx.x;
    const int w    = tid >> 5, lane = tid & 31, g = lane >> 2, tig = lane & 3;
    const unsigned rank = ctarank(), peer = rank ^ 1u;
    const int b0r  = (blockIdx.x >> 1) * TM2;      // cluster id * 16
    const int colb = (int)rank * 128;              // this CTA's N base

    for (int i = tid; i < 4096; i += 512) apack[i] = 0u;   // h_{-1}=0 in buffer 0

    // prefetch Z(0): 16 rows x 128 cols = 512 x 16B chunks, 1 per thread
    {
        int r = tid >> 5, c16 = tid & 31;
        cp_async16(zs + 0 * ZSZ + r * ZSTRIDE + c16 * 4,
                   out + ((size_t)(b0r + r) * S_LEN + 0) * DIM + colb + c16 * 4);
    }
    CP_COMMIT();

    // weight ring: uint2 per kit, depth PFD; global warp id = rank*16 + w
    const unsigned* Bt = g_WhP + ((unsigned)(rank * 16 + w)) * 2048 + lane * 2;
    uint2 pf[PFD];
#pragma unroll
    for (int d = 0; d < PFD; d++)
        pf[d] = *reinterpret_cast<const uint2*>(Bt + d * 64);

    CLUSTER_BAR();   // peer smem initialized before any remote writes

    for (int t = 0; t < S_LEN; t++) {
        const int cb = t & 1, nb = (t + 1) & 1;
        const bool notlast = (t + 1 < S_LEN);

        if (notlast) {
            int r = tid >> 5, c16 = tid & 31;
            cp_async16(zs + nb * ZSZ + r * ZSTRIDE + c16 * 4,
                       out + ((size_t)(b0r + r) * S_LEN + (t + 1)) * DIM + colb + c16 * 4);
        }
        CP_COMMIT();
        CP_WAIT1();          // Z(t) landed
        __syncthreads();     // Z(t) visible to all local threads

        // acc = Z(t): warp covers local cols [8w, 8w+8)
        float acc[4];
        const float* Z = zs + cb * ZSZ;
        {
            int cl = w * 8 + tig * 2;
            float2 v0 = *reinterpret_cast<const float2*>(Z + g * ZSTRIDE + cl);
            float2 v1 = *reinterpret_cast<const float2*>(Z + (g + 8) * ZSTRIDE + cl);
            acc[0] = v0.x; acc[1] = v0.y; acc[2] = v1.x; acc[3] = v1.y;
        }

        // GEMM: 32 kits, 1 LDS.128 + 1 LDG.64 (ring) + 1 MMA per kit
        const unsigned* Acb = apack + cb * 4096;
#pragma unroll
        for (int kit = 0; kit < 32; kit++) {
            uint2 p = pf[kit & (PFD - 1)];
            {
                const int nk = kit + PFD;
                const unsigned* src = (nk < 32)
                    ? (Bt + nk * 64)
                    : (Bt + WT_STRIDE + (nk - 32) * 64);
                if (nk < 32 || notlast)
                    pf[kit & (PFD - 1)] = *reinterpret_cast<const uint2*>(src);
            }
            uint4 a = *reinterpret_cast<const uint4*>(&Acb[kit * 128 + lane * 4]);
            mma_tf32(acc, a.x, a.y, a.z, a.w, p.x, p.y);
        }

        // epilogue: tanh -> out(t); h into apack[nb] of BOTH CTAs.
        // this thread's 4 values: rows {g, g+8} x cols {colb+8w+2tig, +1};
        // global kit for these cols = rank*16 + w.
        {
            const int kit = (int)rank * 16 + w;
            unsigned* An = apack + nb * 4096;
#pragma unroll
            for (int half = 0; half < 2; half++) {
                int rloc = g + half * 8;
                size_t base = ((size_t)(b0r + rloc) * S_LEN + t) * DIM + colb;
                float v0 = fast_tanh(acc[half * 2]);
                float v1 = fast_tanh(acc[half * 2 + 1]);
                int cl = w * 8 + tig * 2;
                *reinterpret_cast<float2*>(out + base + cl) = make_float2(v0, v1);
#pragma unroll
                for (int e = 0; e < 2; e++) {
                    int co = tig * 2 + e;               // 0..7
                    int lp = g * 4 + (co & 3);
                    int j  = (co >= 4 ? 2 : 0) + half;
                    unsigned u = f2tf32(e ? v1 : v0);
                    unsigned off = (unsigned)(kit * 128 + lp * 4 + j);
                    An[off] = u;                                        // local
                    unsigned saddr = (unsigned)__cvta_generic_to_shared(&An[off]);
                    st_remote_u32(saddr, peer, u);                      // peer
                }
            }
        }

        CLUSTER_BAR();   // publish apack[nb] (local + DSMEM) cluster-wide

        Bt += WT_STRIDE;
    }
}

extern "C" void kernel_launch(void* const* d_in, const int* in_sizes, int n_in,
                              void* d_out, int out_size) {
    const float* x  = (const float*)d_in[0];   // [512,512,256]
    const float* Wx = (const float*)d_in[1];   // [512,256,256]
    const float* Wh = (const float*)d_in[2];   // [512,256,256]
    float* out = (float*)d_out;                // [512,512,256]

    unsigned* wxp; cudaGetSymbolAddress((void**)&wxp, g_WxP);
    unsigned* whp; cudaGetSymbolAddress((void**)&whp, g_WhP);

    static int smem_set = 0;
    const int k2_smem = (8192 + 2 * TM2 * ZSTRIDE) * (int)sizeof(unsigned);  // ~49.6KB
    if (!smem_set) {
        cudaFuncSetAttribute(rnn_k2, cudaFuncAttributeMaxDynamicSharedMemorySize, k2_smem);
        smem_set = 1;
    }

    pack_wx<<<32768, 256>>>(Wx, wxp);
    pack_wh<<<65536, 256>>>(Wh, whp);

    dim3 g1(B_SZ / TM1, S_LEN);                    // 16 x 512 CTAs
    rnn_k1<<<g1, 256>>>(x, out);                   // out = Z
    rnn_k2<<<2 * (B_SZ / TM2), 512, k2_smem>>>(out); // 64 CTAs = 32 clusters
}

// round 10
// speedup vs baseline: 1.6423x; 1.6423x over previous
#include <cuda_runtime.h>
#include <cuda_fp16.h>

// RNNBlock: h_t = tanh(x_t @ Wx[t] + h_{t-1} @ Wh[t]), h_{-1}=0
// B=512, S=512, D=256, fp32 in/out.
//
// Compute in fp16 (m16n8k16, fp32 accumulate). fp16 mantissa == tf32 mantissa,
// so accuracy matches the tf32 variant (rel_err ~4e-4) at half the bytes.
//
// K0a: pack Wx -> fp16x2 in K1 consumption order.
// K0b: pack Wh -> fp16x2 in K2 consumption order.
// K1:  out = x @ Wx (parallel, 16x512 CTAs).
// K2:  recurrence, 32 CTAs x 16 rows x 512 threads (16 warps x 16 cols);
//      weights: depth-8 register ring, 1 LDG.128/kit/warp;
//      h in smem as packed fp16 A-frags (1 LDS.128/kit/warp), double-buffered;
//      Z triple-buffered via cp.async; ONE __syncthreads per step.

#define S_LEN 512
#define B_SZ  512
#define DIM   256
#define TM1   32
#define TM2   16
#define XSTR  132              // K1 xs row stride (u32)
#define ZSTR  260              // K2 zs row stride (f32)
#define ZSZ   (TM2 * ZSTR)     // 4160 floats per Z buffer
#define WT4   8192             // uint4 per timestep of packed weights
#define PFD   8                // weight ring depth (kits)

__device__ uint4 g_WxP4[(size_t)S_LEN * WT4];   // 64MB
__device__ uint4 g_WhP4[(size_t)S_LEN * WT4];   // 64MB

__device__ __forceinline__ unsigned pack2h(float lo, float hi) {
    __half2 h = __floats2half2_rn(lo, hi);
    return *reinterpret_cast<unsigned*>(&h);
}

__device__ __forceinline__ void mma_f16(float c[4],
                                        unsigned a0, unsigned a1, unsigned a2, unsigned a3,
                                        unsigned b0, unsigned b1) {
    asm volatile(
        "mma.sync.aligned.m16n8k16.row.col.f32.f16.f16.f32 "
        "{%0,%1,%2,%3}, {%4,%5,%6,%7}, {%8,%9}, {%0,%1,%2,%3};"
        : "+f"(c[0]), "+f"(c[1]), "+f"(c[2]), "+f"(c[3])
        : "r"(a0), "r"(a1), "r"(a2), "r"(a3), "r"(b0), "r"(b1));
}

__device__ __forceinline__ float fast_tanh(float x) {
    x = fminf(fmaxf(x, -15.f), 15.f);
    float e = __expf(2.f * x);
    return __fdividef(e - 1.f, e + 1.f);
}

__device__ __forceinline__ void cp_async16(void* dst_smem, const void* src) {
    unsigned d = (unsigned)__cvta_generic_to_shared(dst_smem);
    asm volatile("cp.async.cg.shared.global [%0], [%1], 16;" :: "r"(d), "l"(src));
}
#define CP_COMMIT() asm volatile("cp.async.commit_group;")
#define CP_WAIT1()  asm volatile("cp.async.wait_group 1;" ::: "memory")

// ---------- K0a: pack Wx (K1 layout) ----------------------------------------------
// uint4 idx = t*8192 + w*1024 + kit*64 + pair*32 + lane   (w<8, kit<16, pair<2)
// n0 = w*32 + pair*16 + g, k0 = kit*16 (g=lane>>2, tig=lane&3):
//  {B[k0+2tig][n0]|B[k0+2tig+1][n0],  B[k0+2tig+8][n0]|B[k0+2tig+9][n0],
//   same for n0+8}
__global__ void __launch_bounds__(256)
pack_wx(const float* __restrict__ W, uint4* __restrict__ P) {
    unsigned idx  = blockIdx.x * 256u + threadIdx.x;
    unsigned lane = idx & 31, pair = (idx >> 5) & 1, kit = (idx >> 6) & 15,
             w    = (idx >> 10) & 7, t = idx >> 13;
    unsigned g = lane >> 2, tig = lane & 3, k0 = kit * 16;
    const float* Wt = W + (size_t)t * DIM * DIM;
    unsigned n0 = w * 32 + pair * 16 + g;
    uint4 v;
    v.x = pack2h(Wt[(k0 + 2*tig)     * DIM + n0],     Wt[(k0 + 2*tig + 1) * DIM + n0]);
    v.y = pack2h(Wt[(k0 + 2*tig + 8) * DIM + n0],     Wt[(k0 + 2*tig + 9) * DIM + n0]);
    v.z = pack2h(Wt[(k0 + 2*tig)     * DIM + n0 + 8], Wt[(k0 + 2*tig + 1) * DIM + n0 + 8]);
    v.w = pack2h(Wt[(k0 + 2*tig + 8) * DIM + n0 + 8], Wt[(k0 + 2*tig + 9) * DIM + n0 + 8]);
    P[idx] = v;
}

// ---------- K0b: pack Wh (K2 layout) ----------------------------------------------
// uint4 idx = t*8192 + w*512 + kit*32 + lane   (w<16, kit<16)
// n0 = w*16 + g, k0 = kit*16; same element formula as pack_wx.
__global__ void __launch_bounds__(256)
pack_wh(const float* __restrict__ W, uint4* __restrict__ P) {
    unsigned idx  = blockIdx.x * 256u + threadIdx.x;
    unsigned lane = idx & 31, kit = (idx >> 5) & 15,
             w    = (idx >> 9) & 15, t = idx >> 13;
    unsigned g = lane >> 2, tig = lane & 3, k0 = kit * 16;
    const float* Wt = W + (size_t)t * DIM * DIM;
    unsigned n0 = w * 16 + g;
    uint4 v;
    v.x = pack2h(Wt[(k0 + 2*tig)     * DIM + n0],     Wt[(k0 + 2*tig + 1) * DIM + n0]);
    v.y = pack2h(Wt[(k0 + 2*tig + 8) * DIM + n0],     Wt[(k0 + 2*tig + 9) * DIM + n0]);
    v.z = pack2h(Wt[(k0 + 2*tig)     * DIM + n0 + 8], Wt[(k0 + 2*tig + 1) * DIM + n0 + 8]);
    v.w = pack2h(Wt[(k0 + 2*tig + 8) * DIM + n0 + 8], Wt[(k0 + 2*tig + 9) * DIM + n0 + 8]);
    P[idx] = v;
}

// ---------- K1: Z = x @ Wx (fp16, 8 warps x 32 cols, 2 M-tiles) --------------------
__global__ void __launch_bounds__(256)
rnn_k1(const float* __restrict__ x, float* __restrict__ out) {
    __shared__ unsigned xs[TM1 * XSTR];          // fp16x2-packed x rows
    const int bt = blockIdx.x, t = blockIdx.y, tid = threadIdx.x;
    const int w = tid >> 5, lane = tid & 31, g = lane >> 2, tig = lane & 3;
    const int b0r = bt * TM1;

    // stage x as packed fp16x2: xs[r][j] = {x[r][2j], x[r][2j+1]}
    for (int i = tid; i < TM1 * (DIM / 4); i += 256) {
        int r = i >> 6, c4 = i & 63;
        float4 v = *reinterpret_cast<const float4*>(
            x + ((size_t)(b0r + r) * S_LEN + t) * DIM + c4 * 4);
        uint2 u = make_uint2(pack2h(v.x, v.y), pack2h(v.z, v.w));
        *reinterpret_cast<uint2*>(&xs[r * XSTR + c4 * 2]) = u;
    }
    __syncthreads();

    float acc[2][4][4] = {};
    const uint4* Bp = g_WxP4 + (size_t)t * WT4 + w * 1024 + lane;
#pragma unroll
    for (int kit = 0; kit < 16; kit++) {
        uint4 p0 = Bp[kit * 64];
        uint4 p1 = Bp[kit * 64 + 32];
        const int kb = kit * 8;                  // u32 col base (16 halves)
        unsigned a[2][4];
#pragma unroll
        for (int mi = 0; mi < 2; mi++) {
            int r0 = mi * 16 + g;
            a[mi][0] = xs[r0 * XSTR + kb + tig];
            a[mi][1] = xs[(r0 + 8) * XSTR + kb + tig];
            a[mi][2] = xs[r0 * XSTR + kb + 4 + tig];
            a[mi][3] = xs[(r0 + 8) * XSTR + kb + 4 + tig];
        }
#pragma unroll
        for (int mi = 0; mi < 2; mi++) {
            mma_f16(acc[mi][0], a[mi][0], a[mi][1], a[mi][2], a[mi][3], p0.x, p0.y);
            mma_f16(acc[mi][1], a[mi][0], a[mi][1], a[mi][2], a[mi][3], p0.z, p0.w);
            mma_f16(acc[mi][2], a[mi][0], a[mi][1], a[mi][2], a[mi][3], p1.x, p1.y);
            mma_f16(acc[mi][3], a[mi][0], a[mi][1], a[mi][2], a[mi][3], p1.z, p1.w);
        }
    }

#pragma unroll
    for (int mi = 0; mi < 2; mi++)
#pragma unroll
        for (int half = 0; half < 2; half++) {
            int r = b0r + mi * 16 + g + half * 8;
            size_t base = ((size_t)r * S_LEN + t) * DIM;
#pragma unroll
            for (int nt = 0; nt < 4; nt++) {
                int c = w * 32 + nt * 8 + tig * 2;
                *reinterpret_cast<float2*>(out + base + c) =
                    make_float2(acc[mi][nt][half * 2], acc[mi][nt][half * 2 + 1]);
            }
        }
}

// ---------- K2: recurrence, 32 CTAs x 512 threads (fp16) ---------------------------
// apack[2][2048] u32: A-frags in mma register order, double-buffered.
//   element: buf*2048 + kit*128 + lane*4 + j
//   j0={h[g][k0+2tig],h[g][k0+2tig+1]}, j1=rows+8, j2=k+8, j3=both (k0=16*kit)
// zs[3][ZSZ] f32: Z stream, triple-buffered (write-issue t+1 never collides with
//   reads of t-1's buffer thanks to 3-way rotation + top-of-step barrier).
__global__ void __launch_bounds__(512, 1)
rnn_k2(float* __restrict__ out) {
    extern __shared__ unsigned smemraw[];
    unsigned* apack = smemraw;                               // 2*2048 u32
    float*    zs    = reinterpret_cast<float*>(smemraw + 4096);

    const int tid = threadIdx.x;
    const int w = tid >> 5, lane = tid & 31, g = lane >> 2, tig = lane & 3;
    const int b0r = blockIdx.x * TM2;

    for (int i = tid; i < 4096; i += 512) apack[i] = 0u;     // h_{-1}=0

    // prefetch Z(0) into zs buffer 0
#pragma unroll
    for (int c = 0; c < 2; c++) {
        int chunk = tid + c * 512;
        int r = chunk >> 6, c16 = chunk & 63;
        cp_async16(zs + 0 * ZSZ + r * ZSTR + c16 * 4,
                   out + ((size_t)(b0r + r) * S_LEN + 0) * DIM + c16 * 4);
    }
    CP_COMMIT();

    // weight ring: 1 uint4 per kit, depth PFD (of 16 kits)
    const uint4* Bt = g_WhP4 + w * 512 + lane;               // += WT4 per t
    uint4 pf[PFD];
#pragma unroll
    for (int d = 0; d < PFD; d++) pf[d] = Bt[d * 32];

    int cb = 0;
    for (int t = 0; t < S_LEN; t++) {
        const int nb = (cb + 1 == 3) ? 0 : cb + 1;
        const bool notlast = (t + 1 < S_LEN);
        const int ab = t & 1;                                // apack read buffer

        if (notlast) {
#pragma unroll
            for (int c = 0; c < 2; c++) {
                int chunk = tid + c * 512;
                int r = chunk >> 6, c16 = chunk & 63;
                cp_async16(zs + nb * ZSZ + r * ZSTR + c16 * 4,
                           out + ((size_t)(b0r + r) * S_LEN + (t + 1)) * DIM + c16 * 4);
            }
        }
        CP_COMMIT();
        CP_WAIT1();          // Z(t) landed
        __syncthreads();     // Z(t) + apack[ab] (epilogue t-1) visible; the ONLY barrier

        // acc = Z(t): warp covers cols [16w, 16w+16)
        float acc[2][4];
        const float* Z = zs + cb * ZSZ;
#pragma unroll
        for (int nt = 0; nt < 2; nt++) {
            int col = w * 16 + nt * 8 + tig * 2;
            float2 v0 = *reinterpret_cast<const float2*>(Z + g * ZSTR + col);
            float2 v1 = *reinterpret_cast<const float2*>(Z + (g + 8) * ZSTR + col);
            acc[nt][0] = v0.x; acc[nt][1] = v0.y;
            acc[nt][2] = v1.x; acc[nt][3] = v1.y;
        }

        // GEMM: 16 kits x (1 LDS.128 + ring LDG.128 + 2 MMA)
        const unsigned* Acb = apack + ab * 2048;
#pragma unroll
        for (int kit = 0; kit < 16; kit++) {
            uint4 p = pf[kit & (PFD - 1)];
            {
                const int nk = kit + PFD;
                if (nk < 16)            pf[kit & (PFD - 1)] = Bt[nk * 32];
                else if (notlast)       pf[kit & (PFD - 1)] = Bt[WT4 + (nk - 16) * 32];
            }
            uint4 a = *reinterpret_cast<const uint4*>(&Acb[kit * 128 + lane * 4]);
            mma_f16(acc[0], a.x, a.y, a.z, a.w, p.x, p.y);
            mma_f16(acc[1], a.x, a.y, a.z, a.w, p.z, p.w);
        }

        // epilogue: tanh -> out(t) fp32; h -> apack[ab^1] as ONE STS.128.
        // cols 16w+nt*8+2tig map to kit'=w, j=2nt+half, lane'=lane.
        {
            float v[2][2][2];                    // [nt][half][e]
#pragma unroll
            for (int nt = 0; nt < 2; nt++)
#pragma unroll
                for (int half = 0; half < 2; half++) {
                    v[nt][half][0] = fast_tanh(acc[nt][half * 2]);
                    v[nt][half][1] = fast_tanh(acc[nt][half * 2 + 1]);
                }
#pragma unroll
            for (int half = 0; half < 2; half++) {
                int r = b0r + g + half * 8;
                size_t base = ((size_t)r * S_LEN + t) * DIM;
#pragma unroll
                for (int nt = 0; nt < 2; nt++) {
                    int col = w * 16 + nt * 8 + tig * 2;
                    *reinterpret_cast<float2*>(out + base + col) =
                        make_float2(v[nt][half][0], v[nt][half][1]);
                }
            }
            uint4 u;
            u.x = pack2h(v[0][0][0], v[0][0][1]);   // j0: nt0, row g
            u.y = pack2h(v[0][1][0], v[0][1][1]);   // j1: nt0, row g+8
            u.z = pack2h(v[1][0][0], v[1][0][1]);   // j2: nt1, row g
            u.w = pack2h(v[1][1][0], v[1][1][1]);   // j3: nt1, row g+8
            *reinterpret_cast<uint4*>(&apack[(ab ^ 1) * 2048 + w * 128 + lane * 4]) = u;
        }

        Bt += WT4;
        cb = nb;
    }
}

extern "C" void kernel_launch(void* const* d_in, const int* in_sizes, int n_in,
                              void* d_out, int out_size) {
    const float* x  = (const float*)d_in[0];   // [512,512,256]
    const float* Wx = (const float*)d_in[1];   // [512,256,256]
    const float* Wh = (const float*)d_in[2];   // [512,256,256]
    float* out = (float*)d_out;                // [512,512,256]

    uint4* wxp; cudaGetSymbolAddress((void**)&wxp, g_WxP4);
    uint4* whp; cudaGetSymbolAddress((void**)&whp, g_WhP4);

    static int smem_set = 0;
    const int k2_smem = (4096 + 3 * ZSZ) * (int)sizeof(unsigned);  // ~66.3KB
    if (!smem_set) {
        cudaFuncSetAttribute(rnn_k2, cudaFuncAttributeMaxDynamicSharedMemorySize, k2_smem);
        smem_set = 1;
    }

    pack_wx<<<16384, 256>>>(Wx, wxp);
    pack_wh<<<16384, 256>>>(Wh, whp);

    dim3 g1(B_SZ / TM1, S_LEN);                // 16 x 512 CTAs
    rnn_k1<<<g1, 256>>>(x, out);               // out = Z
    rnn_k2<<<B_SZ / TM2, 512, k2_smem>>>(out); // out = h (in-place over Z)
}

// round 13
// speedup vs baseline: 1.7558x; 1.0691x over previous
#include <cuda_runtime.h>
#include <cuda_fp16.h>

// RNNBlock: h_t = tanh(x_t @ Wx[t] + h_{t-1} @ Wh[t]), h_{-1}=0
// B=512, S=512, D=256, fp32 in/out.  Compute: fp16 m16n8k16, fp32 accumulate.
//
// K0 (x2): pack Wx/Wh -> fp16x2, 8-warp mma consumption order (shared layout).
// K1:  Z = x @ Wx -> g_ZP (fp16, packed in K2's per-thread accumulator order).
// K2:  recurrence, 32 CTAs x 16 rows x 256 threads (8 warps x 32 cols):
//      weights: depth-8 register ring, 2 LDG.128/kit/warp;
//      h in smem as fp16 A-frags (1 LDS.128/kit/warp), double-buffered;
//      Z: 2 LDS.128/thread from triple-buffered cp.async stream;
//      ONE __syncthreads per step.

#define S_LEN 512
#define B_SZ  512
#define DIM   256
#define TM1   32
#define TM2   16
#define XSTR  132              // K1 xs row stride (u32)
#define WT4   8192             // uint4 per timestep of packed weights
#define PFD   8                // weight ring depth (kits)

__device__ uint4 g_WxP4[(size_t)S_LEN * WT4];          // 64MB
__device__ uint4 g_WhP4[(size_t)S_LEN * WT4];          // 64MB
__device__ uint4 g_ZP[(size_t)32 * S_LEN * 512];       // 134MB fp16 Z, thread-order

__device__ __forceinline__ unsigned pack2h(float lo, float hi) {
    __half2 h = __floats2half2_rn(lo, hi);
    return *reinterpret_cast<unsigned*>(&h);
}

__device__ __forceinline__ void mma_f16(float c[4],
                                        unsigned a0, unsigned a1, unsigned a2, unsigned a3,
                                        unsigned b0, unsigned b1) {
    asm volatile(
        "mma.sync.aligned.m16n8k16.row.col.f32.f16.f16.f32 "
        "{%0,%1,%2,%3}, {%4,%5,%6,%7}, {%8,%9}, {%0,%1,%2,%3};"
        : "+f"(c[0]), "+f"(c[1]), "+f"(c[2]), "+f"(c[3])
        : "r"(a0), "r"(a1), "r"(a2), "r"(a3), "r"(b0), "r"(b1));
}

__device__ __forceinline__ float fast_tanh(float x) {
    x = fminf(fmaxf(x, -15.f), 15.f);
    float e = __expf(2.f * x);
    return __fdividef(e - 1.f, e + 1.f);
}

__device__ __forceinline__ void cp_async16(void* dst_smem, const void* src) {
    unsigned d = (unsigned)__cvta_generic_to_shared(dst_smem);
    asm volatile("cp.async.cg.shared.global [%0], [%1], 16;" :: "r"(d), "l"(src));
}
#define CP_COMMIT() asm volatile("cp.async.commit_group;")
#define CP_WAIT1()  asm volatile("cp.async.wait_group 1;" ::: "memory")

// ---------- K0: pack W (shared 8-warp layout, used for both Wx and Wh) ------------
// uint4 idx = t*8192 + w*1024 + kit*64 + pair*32 + lane   (w<8, kit<16, pair<2)
// n0 = w*32 + pair*16 + g, k0 = kit*16 (g=lane>>2, tig=lane&3):
//  {W[k0+2tig][n0]|W[k0+2tig+1][n0],  W[k0+2tig+8][n0]|W[k0+2tig+9][n0],
//   same pair for n0+8}
__global__ void __launch_bounds__(256)
pack_w(const float* __restrict__ W, uint4* __restrict__ P) {
    unsigned idx  = blockIdx.x * 256u + threadIdx.x;
    unsigned lane = idx & 31, pair = (idx >> 5) & 1, kit = (idx >> 6) & 15,
             w    = (idx >> 10) & 7, t = idx >> 13;
    unsigned g = lane >> 2, tig = lane & 3, k0 = kit * 16;
    const float* Wt = W + (size_t)t * DIM * DIM;
    unsigned n0 = w * 32 + pair * 16 + g;
    uint4 v;
    v.x = pack2h(Wt[(k0 + 2*tig)     * DIM + n0],     Wt[(k0 + 2*tig + 1) * DIM + n0]);
    v.y = pack2h(Wt[(k0 + 2*tig + 8) * DIM + n0],     Wt[(k0 + 2*tig + 9) * DIM + n0]);
    v.z = pack2h(Wt[(k0 + 2*tig)     * DIM + n0 + 8], Wt[(k0 + 2*tig + 1) * DIM + n0 + 8]);
    v.w = pack2h(Wt[(k0 + 2*tig + 8) * DIM + n0 + 8], Wt[(k0 + 2*tig + 9) * DIM + n0 + 8]);
    P[idx] = v;
}

// ---------- K1: Z = x @ Wx -> g_ZP (fp16, K2-thread order) -------------------------
// ZP uint4 index: ((bt16*512 + t)*8 + w)*64 + j*32 + lane,  j in {0,1}
//   j=0 holds q0..q3 (nt0,nt1), j=1 holds q4..q7 (nt2,nt3), where
//   q[2nt]   = {v[row g  ][col 32w+8nt+2tig], v[row g  ][col+1]}
//   q[2nt+1] = {v[row g+8][col 32w+8nt+2tig], v[row g+8][col+1]}
__global__ void __launch_bounds__(256)
rnn_k1(const float* __restrict__ x, uint4* __restrict__ ZP) {
    __shared__ unsigned xs[TM1 * XSTR];          // fp16x2-packed x rows
    const int bt = blockIdx.x, t = blockIdx.y, tid = threadIdx.x;
    const int w = tid >> 5, lane = tid & 31, g = lane >> 2, tig = lane & 3;
    const int b0r = bt * TM1;

    for (int i = tid; i < TM1 * (DIM / 4); i += 256) {
        int r = i >> 6, c4 = i & 63;
        float4 v = *reinterpret_cast<const float4*>(
            x + ((size_t)(b0r + r) * S_LEN + t) * DIM + c4 * 4);
        uint2 u = make_uint2(pack2h(v.x, v.y), pack2h(v.z, v.w));
        *reinterpret_cast<uint2*>(&xs[r * XSTR + c4 * 2]) = u;
    }
    __syncthreads();

    float acc[2][4][4] = {};
    const uint4* Bp = g_WxP4 + (size_t)t * WT4 + w * 1024 + lane;
#pragma unroll
    for (int kit = 0; kit < 16; kit++) {
        uint4 p0 = Bp[kit * 64];
        uint4 p1 = Bp[kit * 64 + 32];
        const int kb = kit * 8;
        unsigned a[2][4];
#pragma unroll
        for (int mi = 0; mi < 2; mi++) {
            int r0 = mi * 16 + g;
            a[mi][0] = xs[r0 * XSTR + kb + tig];
            a[mi][1] = xs[(r0 + 8) * XSTR + kb + tig];
            a[mi][2] = xs[r0 * XSTR + kb + 4 + tig];
            a[mi][3] = xs[(r0 + 8) * XSTR + kb + 4 + tig];
        }
#pragma unroll
        for (int mi = 0; mi < 2; mi++) {
            mma_f16(acc[mi][0], a[mi][0], a[mi][1], a[mi][2], a[mi][3], p0.x, p0.y);
            mma_f16(acc[mi][1], a[mi][0], a[mi][1], a[mi][2], a[mi][3], p0.z, p0.w);
            mma_f16(acc[mi][2], a[mi][0], a[mi][1], a[mi][2], a[mi][3], p1.x, p1.y);
            mma_f16(acc[mi][3], a[mi][0], a[mi][1], a[mi][2], a[mi][3], p1.z, p1.w);
        }
    }

#pragma unroll
    for (int mi = 0; mi < 2; mi++) {
        const int bt16 = 2 * bt + mi;
        uint4* dst = ZP + ((size_t)(bt16 * S_LEN + t) * 8 + w) * 64 + lane;
        uint4 u0, u1;
        u0.x = pack2h(acc[mi][0][0], acc[mi][0][1]);
        u0.y = pack2h(acc[mi][0][2], acc[mi][0][3]);
        u0.z = pack2h(acc[mi][1][0], acc[mi][1][1]);
        u0.w = pack2h(acc[mi][1][2], acc[mi][1][3]);
        u1.x = pack2h(acc[mi][2][0], acc[mi][2][1]);
        u1.y = pack2h(acc[mi][2][2], acc[mi][2][3]);
        u1.z = pack2h(acc[mi][3][0], acc[mi][3][1]);
        u1.w = pack2h(acc[mi][3][2], acc[mi][3][3]);
        dst[0]  = u0;
        dst[32] = u1;
    }
}

// ---------- K2: recurrence, 32 CTAs x 256 threads (8 warps x 32 cols) --------------
// apack[2][2048] u32: A-frags in mma register order, double-buffered.
//   element: buf*2048 + kit*128 + lane*4 + j   (16 kits)
//   j0={h[g][k0+2tig],+1}, j1=rows+8, j2=k+8 row g, j3=k+8 rows+8 (k0=16*kit)
// zq[3][512] uint4: Z stream (fp16, thread-order), triple-buffered.
__global__ void __launch_bounds__(256, 1)
rnn_k2(const uint4* __restrict__ ZP, float* __restrict__ out) {
    __shared__ unsigned apack[2 * 2048];                 // 16KB
    __shared__ uint4    zq[3 * 512];                     // 24KB

    const int tid = threadIdx.x;
    const int w = tid >> 5, lane = tid & 31, g = lane >> 2, tig = lane & 3;
    const int bt = blockIdx.x;
    const int b0r = bt * TM2;

    for (int i = tid; i < 4096; i += 256) apack[i] = 0u;     // h_{-1}=0

    // prefetch Z(0) into zq buffer 0 (512 uint4, 2 per thread)
    {
        const uint4* src = g_ZP + (size_t)(bt * S_LEN + 0) * 512;
        cp_async16(&zq[0 * 512 + tid],       src + tid);
        cp_async16(&zq[0 * 512 + tid + 256], src + tid + 256);
    }
    CP_COMMIT();

    // weight ring: 2 uint4 per kit, depth PFD (of 16 kits)
    const uint4* Bt = g_WhP4 + w * 1024 + lane;              // += WT4 per t
    uint4 pf[PFD][2];
#pragma unroll
    for (int d = 0; d < PFD; d++) {
        pf[d][0] = Bt[d * 64];
        pf[d][1] = Bt[d * 64 + 32];
    }

    int cb = 0;
    for (int t = 0; t < S_LEN; t++) {
        const int nb = (cb + 1 == 3) ? 0 : cb + 1;
        const bool notlast = (t + 1 < S_LEN);
        const int ab = t & 1;                                // apack read buffer

        if (notlast) {
            const uint4* src = g_ZP + (size_t)(bt * S_LEN + (t + 1)) * 512;
            cp_async16(&zq[nb * 512 + tid],       src + tid);
            cp_async16(&zq[nb * 512 + tid + 256], src + tid + 256);
        }
        CP_COMMIT();
        CP_WAIT1();          // Z(t) landed
        __syncthreads();     // Z(t) + apack[ab] (epilogue t-1) visible; ONLY barrier

        // acc = Z(t): 2 conflict-free LDS.128, convert fp16 -> fp32
        float acc[4][4];
        {
            const uint4* Zb = &zq[cb * 512 + w * 64 + lane];
            uint4 z0 = Zb[0], z1 = Zb[32];
            const __half2* zh0 = reinterpret_cast<const __half2*>(&z0);
            const __half2* zh1 = reinterpret_cast<const __half2*>(&z1);
#pragma unroll
            for (int nt = 0; nt < 2; nt++) {
                float2 lo = __half22float2(zh0[2 * nt]);
                float2 hi = __half22float2(zh0[2 * nt + 1]);
                acc[nt][0] = lo.x; acc[nt][1] = lo.y;
                acc[nt][2] = hi.x; acc[nt][3] = hi.y;
            }
#pragma unroll
            for (int nt = 0; nt < 2; nt++) {
                float2 lo = __half22float2(zh1[2 * nt]);
                float2 hi = __half22float2(zh1[2 * nt + 1]);
                acc[nt + 2][0] = lo.x; acc[nt + 2][1] = lo.y;
                acc[nt + 2][2] = hi.x; acc[nt + 2][3] = hi.y;
            }
        }

        // GEMM: 16 kits x (1 LDS.128 A + 2 ring LDG.128 + 4 MMA)
        const unsigned* Acb = apack + ab * 2048;
#pragma unroll
        for (int kit = 0; kit < 16; kit++) {
            uint4 p0 = pf[kit & (PFD - 1)][0];
            uint4 p1 = pf[kit & (PFD - 1)][1];
            {
                const int nk = kit + PFD;
                if (nk < 16) {
                    pf[kit & (PFD - 1)][0] = Bt[nk * 64];
                    pf[kit & (PFD - 1)][1] = Bt[nk * 64 + 32];
                } else if (notlast) {
                    pf[kit & (PFD - 1)][0] = Bt[WT4 + (nk - 16) * 64];
                    pf[kit & (PFD - 1)][1] = Bt[WT4 + (nk - 16) * 64 + 32];
                }
            }
            uint4 a = *reinterpret_cast<const uint4*>(&Acb[kit * 128 + lane * 4]);
            mma_f16(acc[0], a.x, a.y, a.z, a.w, p0.x, p0.y);
            mma_f16(acc[1], a.x, a.y, a.z, a.w, p0.z, p0.w);
            mma_f16(acc[2], a.x, a.y, a.z, a.w, p1.x, p1.y);
            mma_f16(acc[3], a.x, a.y, a.z, a.w, p1.z, p1.w);
        }

        // epilogue: tanh; fp32 -> out(t); fp16 A-frags -> apack[ab^1] (2 STS.128)
        {
            float tv[4][4];
#pragma unroll
            for (int nt = 0; nt < 4; nt++)
#pragma unroll
                for (int j = 0; j < 4; j++)
                    tv[nt][j] = fast_tanh(acc[nt][j]);

#pragma unroll
            for (int half = 0; half < 2; half++) {
                int r = b0r + g + half * 8;
                size_t base = ((size_t)r * S_LEN + t) * DIM;
#pragma unroll
                for (int nt = 0; nt < 4; nt++) {
                    int col = w * 32 + nt * 8 + tig * 2;
                    *reinterpret_cast<float2*>(out + base + col) =
                        make_float2(tv[nt][half * 2], tv[nt][half * 2 + 1]);
                }
            }

            unsigned* An = apack + (ab ^ 1) * 2048;
            uint4 u0, u1;
            u0.x = pack2h(tv[0][0], tv[0][1]);   // kit 2w:   j0 (row g,   k-lo)
            u0.y = pack2h(tv[0][2], tv[0][3]);   //           j1 (row g+8, k-lo)
            u0.z = pack2h(tv[1][0], tv[1][1]);   //           j2 (row g,   k-hi)
            u0.w = pack2h(tv[1][2], tv[1][3]);   //           j3 (row g+8, k-hi)
            u1.x = pack2h(tv[2][0], tv[2][1]);   // kit 2w+1
            u1.y = pack2h(tv[2][2], tv[2][3]);
            u1.z = pack2h(tv[3][0], tv[3][1]);
            u1.w = pack2h(tv[3][2], tv[3][3]);
            *reinterpret_cast<uint4*>(&An[(2 * w)     * 128 + lane * 4]) = u0;
            *reinterpret_cast<uint4*>(&An[(2 * w + 1) * 128 + lane * 4]) = u1;
        }

        Bt += WT4;
        cb = nb;
    }
}

extern "C" void kernel_launch(void* const* d_in, const int* in_sizes, int n_in,
                              void* d_out, int out_size) {
    const float* x  = (const float*)d_in[0];   // [512,512,256]
    const float* Wx = (const float*)d_in[1];   // [512,256,256]
    const float* Wh = (const float*)d_in[2];   // [512,256,256]
    float* out = (float*)d_out;                // [512,512,256]

    uint4* wxp; cudaGetSymbolAddress((void**)&wxp, g_WxP4);
    uint4* whp; cudaGetSymbolAddress((void**)&whp, g_WhP4);
    uint4* zp;  cudaGetSymbolAddress((void**)&zp,  g_ZP);

    pack_w<<<16384, 256>>>(Wx, wxp);
    pack_w<<<16384, 256>>>(Wh, whp);

    dim3 g1(B_SZ / TM1, S_LEN);                // 16 x 512 CTAs
    rnn_k1<<<g1, 256>>>(x, zp);                // ZP = x @ Wx (fp16, thread-order)
    rnn_k2<<<B_SZ / TM2, 256>>>(zp, out);      // out = h
}

// round 14
// speedup vs baseline: 1.8652x; 1.0623x over previous
#include <cuda_runtime.h>
#include <cuda_fp16.h>

// RNNBlock: h_t = tanh(x_t @ Wx[t] + h_{t-1} @ Wh[t]), h_{-1}=0
// B=512, S=512, D=256, fp32 in/out.  Compute: fp16 m16n8k16, fp32 accumulate.
//
// K0 (x2): pack Wx/Wh -> fp16x2, 8-colgroup mma consumption order.
// K1:  Z = x @ Wx -> g_ZP (fp16, packed in K2's per-thread accumulator order).
// K2:  recurrence, 32 CTAs x 16 rows x 512 threads, K-SPLIT:
//      warp pair (w, w+8) covers cols [32w,32w+32); lo warp = kits 0-7,
//      hi warp = kits 8-15 (seeded from Z). Hi stores fp32 partials to smem;
//      lo adds, tanh, writes out + next-step A-frags. 4 warps/SMSP in the
//      GEMM phase for latency hiding; depth-4 weight register ring.

#define S_LEN 512
#define B_SZ  512
#define DIM   256
#define TM1   32
#define TM2   16
#define XSTR  132              // K1 xs row stride (u32)
#define WT4   8192             // uint4 per timestep of packed weights
#define PFD   4                // weight ring depth (local kits)

__device__ uint4 g_WxP4[(size_t)S_LEN * WT4];          // 64MB
__device__ uint4 g_WhP4[(size_t)S_LEN * WT4];          // 64MB
__device__ uint4 g_ZP[(size_t)32 * S_LEN * 512];       // 134MB fp16 Z, thread-order

__device__ __forceinline__ unsigned pack2h(float lo, float hi) {
    __half2 h = __floats2half2_rn(lo, hi);
    return *reinterpret_cast<unsigned*>(&h);
}

__device__ __forceinline__ void mma_f16(float c[4],
                                        unsigned a0, unsigned a1, unsigned a2, unsigned a3,
                                        unsigned b0, unsigned b1) {
    asm volatile(
        "mma.sync.aligned.m16n8k16.row.col.f32.f16.f16.f32 "
        "{%0,%1,%2,%3}, {%4,%5,%6,%7}, {%8,%9}, {%0,%1,%2,%3};"
        : "+f"(c[0]), "+f"(c[1]), "+f"(c[2]), "+f"(c[3])
        : "r"(a0), "r"(a1), "r"(a2), "r"(a3), "r"(b0), "r"(b1));
}

__device__ __forceinline__ float fast_tanh(float x) {
    x = fminf(fmaxf(x, -15.f), 15.f);
    float e = __expf(2.f * x);
    return __fdividef(e - 1.f, e + 1.f);
}

__device__ __forceinline__ void cp_async16(void* dst_smem, const void* src) {
    unsigned d = (unsigned)__cvta_generic_to_shared(dst_smem);
    asm volatile("cp.async.cg.shared.global [%0], [%1], 16;" :: "r"(d), "l"(src));
}
#define CP_COMMIT() asm volatile("cp.async.commit_group;")
#define CP_WAIT1()  asm volatile("cp.async.wait_group 1;" ::: "memory")

// ---------- K0: pack W (8-colgroup layout, used for both Wx and Wh) ---------------
// uint4 idx = t*8192 + w*1024 + kit*64 + pair*32 + lane   (w<8, kit<16, pair<2)
// n0 = w*32 + pair*16 + g, k0 = kit*16 (g=lane>>2, tig=lane&3):
//  {W[k0+2tig][n0]|W[k0+2tig+1][n0],  W[k0+2tig+8][n0]|W[k0+2tig+9][n0],
//   same pair for n0+8}
__global__ void __launch_bounds__(256)
pack_w(const float* __restrict__ W, uint4* __restrict__ P) {
    unsigned idx  = blockIdx.x * 256u + threadIdx.x;
    unsigned lane = idx & 31, pair = (idx >> 5) & 1, kit = (idx >> 6) & 15,
             w    = (idx >> 10) & 7, t = idx >> 13;
    unsigned g = lane >> 2, tig = lane & 3, k0 = kit * 16;
    const float* Wt = W + (size_t)t * DIM * DIM;
    unsigned n0 = w * 32 + pair * 16 + g;
    uint4 v;
    v.x = pack2h(Wt[(k0 + 2*tig)     * DIM + n0],     Wt[(k0 + 2*tig + 1) * DIM + n0]);
    v.y = pack2h(Wt[(k0 + 2*tig + 8) * DIM + n0],     Wt[(k0 + 2*tig + 9) * DIM + n0]);
    v.z = pack2h(Wt[(k0 + 2*tig)     * DIM + n0 + 8], Wt[(k0 + 2*tig + 1) * DIM + n0 + 8]);
    v.w = pack2h(Wt[(k0 + 2*tig + 8) * DIM + n0 + 8], Wt[(k0 + 2*tig + 9) * DIM + n0 + 8]);
    P[idx] = v;
}

// ---------- K1: Z = x @ Wx -> g_ZP (fp16, K2-thread order) -------------------------
// ZP uint4 index: ((bt16*512 + t)*8 + w)*64 + j*32 + lane,  j in {0,1}
__global__ void __launch_bounds__(256)
rnn_k1(const float* __restrict__ x, uint4* __restrict__ ZP) {
    __shared__ unsigned xs[TM1 * XSTR];          // fp16x2-packed x rows
    const int bt = blockIdx.x, t = blockIdx.y, tid = threadIdx.x;
    const int w = tid >> 5, lane = tid & 31, g = lane >> 2, tig = lane & 3;
    const int b0r = bt * TM1;

    for (int i = tid; i < TM1 * (DIM / 4); i += 256) {
        int r = i >> 6, c4 = i & 63;
        float4 v = *reinterpret_cast<const float4*>(
            x + ((size_t)(b0r + r) * S_LEN + t) * DIM + c4 * 4);
        uint2 u = make_uint2(pack2h(v.x, v.y), pack2h(v.z, v.w));
        *reinterpret_cast<uint2*>(&xs[r * XSTR + c4 * 2]) = u;
    }
    __syncthreads();

    float acc[2][4][4] = {};
    const uint4* Bp = g_WxP4 + (size_t)t * WT4 + w * 1024 + lane;
#pragma unroll
    for (int kit = 0; kit < 16; kit++) {
        uint4 p0 = Bp[kit * 64];
        uint4 p1 = Bp[kit * 64 + 32];
        const int kb = kit * 8;
        unsigned a[2][4];
#pragma unroll
        for (int mi = 0; mi < 2; mi++) {
            int r0 = mi * 16 + g;
            a[mi][0] = xs[r0 * XSTR + kb + tig];
            a[mi][1] = xs[(r0 + 8) * XSTR + kb + tig];
            a[mi][2] = xs[r0 * XSTR + kb + 4 + tig];
            a[mi][3] = xs[(r0 + 8) * XSTR + kb + 4 + tig];
        }
#pragma unroll
        for (int mi = 0; mi < 2; mi++) {
            mma_f16(acc[mi][0], a[mi][0], a[mi][1], a[mi][2], a[mi][3], p0.x, p0.y);
            mma_f16(acc[mi][1], a[mi][0], a[mi][1], a[mi][2], a[mi][3], p0.z, p0.w);
            mma_f16(acc[mi][2], a[mi][0], a[mi][1], a[mi][2], a[mi][3], p1.x, p1.y);
            mma_f16(acc[mi][3], a[mi][0], a[mi][1], a[mi][2], a[mi][3], p1.z, p1.w);
        }
    }

#pragma unroll
    for (int mi = 0; mi < 2; mi++) {
        const int bt16 = 2 * bt + mi;
        uint4* dst = ZP + ((size_t)(bt16 * S_LEN + t) * 8 + w) * 64 + lane;
        uint4 u0, u1;
        u0.x = pack2h(acc[mi][0][0], acc[mi][0][1]);
        u0.y = pack2h(acc[mi][0][2], acc[mi][0][3]);
        u0.z = pack2h(acc[mi][1][0], acc[mi][1][1]);
        u0.w = pack2h(acc[mi][1][2], acc[mi][1][3]);
        u1.x = pack2h(acc[mi][2][0], acc[mi][2][1]);
        u1.y = pack2h(acc[mi][2][2], acc[mi][2][3]);
        u1.z = pack2h(acc[mi][3][0], acc[mi][3][1]);
        u1.w = pack2h(acc[mi][3][2], acc[mi][3][3]);
        dst[0]  = u0;
        dst[32] = u1;
    }
}

// ---------- K2: recurrence, 32 CTAs x 512 threads, K-split -------------------------
// smem: apack[2][2048] u32 (A-frags, mma register order, double-buffered);
//       zq[3][512] uint4 (fp16 Z stream, triple-buffered);
//       pred[8][4][32] float4 (hi-warp fp32 partials).
__global__ void __launch_bounds__(512, 1)
rnn_k2(const uint4* __restrict__ ZP, float* __restrict__ out) {
    extern __shared__ unsigned smemraw[];
    unsigned* apack = smemraw;                                    // 4096 u32, 16KB
    uint4*    zq    = reinterpret_cast<uint4*>(smemraw + 4096);   // 1536 uint4, 24KB
    float4*   pred  = reinterpret_cast<float4*>(zq + 1536);       // 1024 float4, 16KB

    const int tid  = threadIdx.x;
    const int w    = tid >> 5, lane = tid & 31;
    const int g    = lane >> 2, tig = lane & 3;
    const int colw = w & 7;              // column group: cols [32*colw, +32)
    const int kb   = (w >> 3) * 8;       // kit base: 0 (lo) or 8 (hi)
    const bool hiw = (w >= 8);
    const int bt   = blockIdx.x;
    const int b0r  = bt * TM2;

    for (int i = tid; i < 4096; i += 512) apack[i] = 0u;          // h_{-1}=0

    // prefetch Z(0) into zq buffer 0 (512 uint4, 1 per thread)
    cp_async16(&zq[tid], g_ZP + (size_t)(bt * S_LEN) * 512 + tid);
    CP_COMMIT();

    // weight ring: this warp's 8 local kits, depth-4 ring, 2 uint4/kit
    const uint4* Bt = g_WhP4 + (colw * 1024 + kb * 64) + lane;    // += WT4 per t
    uint4 pf[PFD][2];
#pragma unroll
    for (int d = 0; d < PFD; d++) {
        pf[d][0] = Bt[d * 64];
        pf[d][1] = Bt[d * 64 + 32];
    }

    int cb = 0;
    for (int t = 0; t < S_LEN; t++) {
        const int nb = (cb + 1 == 3) ? 0 : cb + 1;
        const bool notlast = (t + 1 < S_LEN);
        const int ab = t & 1;                                     // apack read buffer

        if (notlast)
            cp_async16(&zq[nb * 512 + tid],
                       g_ZP + (size_t)(bt * S_LEN + t + 1) * 512 + tid);
        CP_COMMIT();
        CP_WAIT1();          // Z(t) landed
        __syncthreads();     // Z(t) + apack[ab] (epilogue t-1) visible

        // seed accumulators: hi warps from Z(t), lo warps from 0
        float acc[4][4];
        if (hiw) {
            const uint4* Zb = &zq[cb * 512 + colw * 64 + lane];
            uint4 z0 = Zb[0], z1 = Zb[32];
            const __half2* zh0 = reinterpret_cast<const __half2*>(&z0);
            const __half2* zh1 = reinterpret_cast<const __half2*>(&z1);
#pragma unroll
            for (int nt = 0; nt < 2; nt++) {
                float2 lo = __half22float2(zh0[2 * nt]);
                float2 hi = __half22float2(zh0[2 * nt + 1]);
                acc[nt][0] = lo.x; acc[nt][1] = lo.y;
                acc[nt][2] = hi.x; acc[nt][3] = hi.y;
            }
#pragma unroll
            for (int nt = 0; nt < 2; nt++) {
                float2 lo = __half22float2(zh1[2 * nt]);
                float2 hi = __half22float2(zh1[2 * nt + 1]);
                acc[nt + 2][0] = lo.x; acc[nt + 2][1] = lo.y;
                acc[nt + 2][2] = hi.x; acc[nt + 2][3] = hi.y;
            }
        } else {
#pragma unroll
            for (int nt = 0; nt < 4; nt++)
#pragma unroll
                for (int j = 0; j < 4; j++) acc[nt][j] = 0.f;
        }

        // GEMM: 8 local kits x (1 LDS.128 A + 2 ring LDG.128 + 4 MMA)
        const unsigned* Acb = apack + ab * 2048;
#pragma unroll
        for (int i = 0; i < 8; i++) {
            uint4 p0 = pf[i & (PFD - 1)][0];
            uint4 p1 = pf[i & (PFD - 1)][1];
            {
                const int nk = i + PFD;
                if (nk < 8) {
                    pf[i & (PFD - 1)][0] = Bt[nk * 64];
                    pf[i & (PFD - 1)][1] = Bt[nk * 64 + 32];
                } else if (notlast) {
                    pf[i & (PFD - 1)][0] = Bt[WT4 + (nk - 8) * 64];
                    pf[i & (PFD - 1)][1] = Bt[WT4 + (nk - 8) * 64 + 32];
                }
            }
            uint4 a = *reinterpret_cast<const uint4*>(&Acb[(kb + i) * 128 + lane * 4]);
            mma_f16(acc[0], a.x, a.y, a.z, a.w, p0.x, p0.y);
            mma_f16(acc[1], a.x, a.y, a.z, a.w, p0.z, p0.w);
            mma_f16(acc[2], a.x, a.y, a.z, a.w, p1.x, p1.y);
            mma_f16(acc[3], a.x, a.y, a.z, a.w, p1.z, p1.w);
        }

        // hi warps publish fp32 partials (incl. Z seed); conflict-free STS.128
        if (hiw) {
#pragma unroll
            for (int nt = 0; nt < 4; nt++)
                pred[(colw * 4 + nt) * 32 + lane] =
                    make_float4(acc[nt][0], acc[nt][1], acc[nt][2], acc[nt][3]);
        }
        __syncthreads();     // partials visible; also: all A-frag reads of step t done

        // lo warps: reduce, tanh, write out(t) + apack[ab^1]
        if (!hiw) {
#pragma unroll
            for (int nt = 0; nt < 4; nt++) {
                float4 p = pred[(colw * 4 + nt) * 32 + lane];
                acc[nt][0] += p.x; acc[nt][1] += p.y;
                acc[nt][2] += p.z; acc[nt][3] += p.w;
            }

            float tv[4][4];
#pragma unroll
            for (int nt = 0; nt < 4; nt++)
#pragma unroll
                for (int j = 0; j < 4; j++)
                    tv[nt][j] = fast_tanh(acc[nt][j]);

#pragma unroll
            for (int half = 0; half < 2; half++) {
                int r = b0r + g + half * 8;
                size_t base = ((size_t)r * S_LEN + t) * DIM;
#pragma unroll
                for (int nt = 0; nt < 4; nt++) {
                    int col = colw * 32 + nt * 8 + tig * 2;
                    *reinterpret_cast<float2*>(out + base + col) =
                        make_float2(tv[nt][half * 2], tv[nt][half * 2 + 1]);
                }
            }

            unsigned* An = apack + (ab ^ 1) * 2048;
            uint4 u0, u1;
            u0.x = pack2h(tv[0][0], tv[0][1]);   // kit 2*colw:   j0 (row g,   k-lo)
            u0.y = pack2h(tv[0][2], tv[0][3]);   //              j1 (row g+8, k-lo)
            u0.z = pack2h(tv[1][0], tv[1][1]);   //              j2 (row g,   k-hi)
            u0.w = pack2h(tv[1][2], tv[1][3]);   //              j3 (row g+8, k-hi)
            u1.x = pack2h(tv[2][0], tv[2][1]);   // kit 2*colw+1
            u1.y = pack2h(tv[2][2], tv[2][3]);
            u1.z = pack2h(tv[3][0], tv[3][1]);
            u1.w = pack2h(tv[3][2], tv[3][3]);
            *reinterpret_cast<uint4*>(&An[(2 * colw)     * 128 + lane * 4]) = u0;
            *reinterpret_cast<uint4*>(&An[(2 * colw + 1) * 128 + lane * 4]) = u1;
        }

        Bt += WT4;
        cb = nb;
    }
}

extern "C" void kernel_launch(void* const* d_in, const int* in_sizes, int n_in,
                              void* d_out, int out_size) {
    const float* x  = (const float*)d_in[0];   // [512,512,256]
    const float* Wx = (const float*)d_in[1];   // [512,256,256]
    const float* Wh = (const float*)d_in[2];   // [512,256,256]
    float* out = (float*)d_out;                // [512,512,256]

    uint4* wxp; cudaGetSymbolAddress((void**)&wxp, g_WxP4);
    uint4* whp; cudaGetSymbolAddress((void**)&whp, g_WhP4);
    uint4* zp;  cudaGetSymbolAddress((void**)&zp,  g_ZP);

    static int smem_set = 0;
    const int k2_smem = 16384 + 24576 + 16384;   // apack + zq + pred = 57344 B
    if (!smem_set) {
        cudaFuncSetAttribute(rnn_k2, cudaFuncAttributeMaxDynamicSharedMemorySize, k2_smem);
        smem_set = 1;
    }

    pack_w<<<16384, 256>>>(Wx, wxp);
    pack_w<<<16384, 256>>>(Wh, whp);

    dim3 g1(B_SZ / TM1, S_LEN);                    // 16 x 512 CTAs
    rnn_k1<<<g1, 256>>>(x, zp);                    // ZP = x @ Wx (fp16, thread-order)
    rnn_k2<<<B_SZ / TM2, 512, k2_smem>>>(zp, out); // out = h
}